// round 16
// baseline (speedup 1.0000x reference)
#include <cuda_runtime.h>
#include <cuda_bf16.h>

// PrototypeLoss: out = mean_i ||features[i] - prototypes[labels[i]]||^2
// N=131072, D=512, C=1000.
//
// R15 analysis: kernel sits exactly at the LTS cap (~11.3 TB/s total L2
// traffic: 268MB feature DRAM stream + 268MB f32 prototype gathers).
// DRAM% (73%) is just the feature share of that cap. Fix: convert the 2MB
// prototype table to bf16 once (pre-kernel), halving gather bytes ->
// LTS traffic 536->402MB, DRAM becomes the binder (~94% of spec needed).
// bf16 proto rounding adds ~1e-6 relative bias (tolerance 1e-3).
//
// inputs identified by element count:
//   features f32 [N,D]=67108864, labels int [N]=131072 (dtype sniffed),
//   protos f32 [C,D]=512000.  output: f32 [1,1]

#define N_ROWS 131072
#define N_CLASSES 1000
#define D_VEC  128                 // D/4 float4 per row
#define BLOCKS_PER_SM 6
#define GRID_BLOCKS (148 * BLOCKS_PER_SM)   // 888 = one full wave
#define BLOCK_THREADS 256
#define WARPS_TOTAL ((GRID_BLOCKS * BLOCK_THREADS) >> 5)          // 7104
#define MAX_ITERS ((N_ROWS + WARPS_TOTAL - 1) / WARPS_TOTAL)      // 19

__device__ __nv_bfloat16 g_pbf[N_CLASSES * 512];   // bf16 prototype table (1MB)
__device__ float    g_partials[GRID_BLOCKS];
__device__ unsigned g_done;   // zero-init at load; reset by last block each run

// ---------- K1: f32 -> bf16 prototype conversion (2MB read, 1MB write) ------
__global__ __launch_bounds__(256)
void convert_kernel(const float4* __restrict__ protos) {
    const int i = blockIdx.x * blockDim.x + threadIdx.x;   // one float4 each
    if (i < N_CLASSES * D_VEC) {
        float4 v = protos[i];
        __nv_bfloat162 lo = __floats2bfloat162_rn(v.x, v.y);
        __nv_bfloat162 hi = __floats2bfloat162_rn(v.z, v.w);
        ((__nv_bfloat162*)g_pbf)[2 * i]     = lo;
        ((__nv_bfloat162*)g_pbf)[2 * i + 1] = hi;
    }
}

// ---------- K2: main streaming gather-reduction -----------------------------
__device__ __forceinline__ float row_dist_bf(const float4* __restrict__ f,
                                             const uint2* __restrict__ p2,
                                             int lane) {
    float acc = 0.0f;
    #pragma unroll
    for (int j = 0; j < 4; j++) {
        const int idx = lane + j * 32;
        float4 a = f[idx];
        uint2  pb = p2[idx];                       // 4 bf16 = same dims as a
        float2 p01 = __bfloat1622float2(*(const __nv_bfloat162*)&pb.x);
        float2 p23 = __bfloat1622float2(*(const __nv_bfloat162*)&pb.y);
        float dx = a.x - p01.x;
        float dy = a.y - p01.y;
        float dz = a.z - p23.x;
        float dw = a.w - p23.y;
        acc = fmaf(dx, dx, acc);
        acc = fmaf(dy, dy, acc);
        acc = fmaf(dz, dz, acc);
        acc = fmaf(dw, dw, acc);
    }
    return acc;
}

__global__ __launch_bounds__(BLOCK_THREADS, BLOCKS_PER_SM)
void proto_loss_kernel(const float4* __restrict__ feat,
                       const void* __restrict__ labels_raw,
                       float* __restrict__ out) {
    const int lane = threadIdx.x & 31;
    const int wid  = threadIdx.x >> 5;

    __shared__ int   s_is64;
    __shared__ float ssum[BLOCK_THREADS / 32];
    __shared__ int   s_last;

    // --- Label dtype sniff (warp 0): for int64 labels in [0,1000), the odd
    // 32-bit words of the first 64 entries are all zero. For int32 that needs
    // 64 specific labels == 0 (p ~ 1e-192).
    if (wid == 0) {
        const unsigned* lw = (const unsigned*)labels_raw;
        unsigned w = lw[2 * lane + 1] | lw[2 * lane + 65];
        #pragma unroll
        for (int off = 16; off; off >>= 1)
            w |= __shfl_xor_sync(0xFFFFFFFFu, w, off);
        if (lane == 0) s_is64 = (w == 0u) ? 1 : 0;
    }
    __syncthreads();
    const int is64 = s_is64;
    const int*       l32 = (const int*)labels_raw;
    const long long* l64 = (const long long*)labels_raw;

    const int gwarp = (blockIdx.x * BLOCK_THREADS + threadIdx.x) >> 5;

    // --- Preload this warp's labels: lane k holds the label for iteration k
    // (MAX_ITERS=19 <= 32). No label load in the hot loop.
    int mylbl = 0;
    {
        const int myrow = gwarp + lane * WARPS_TOTAL;
        if (lane < MAX_ITERS && myrow < N_ROWS) {
            int l = is64 ? (int)l64[myrow] : l32[myrow];
            mylbl = (l < 0) ? 0 : (l >= N_CLASSES ? N_CLASSES - 1 : l);
        }
    }

    float acc = 0.0f;

    #pragma unroll
    for (int it = 0; it < MAX_ITERS; it++) {
        const int row = gwarp + it * WARPS_TOTAL;
        const int lbl = __shfl_sync(0xFFFFFFFFu, mylbl, it);
        if (row < N_ROWS) {
            const float4* f  = feat + (size_t)row * D_VEC;
            const uint2*  p2 = (const uint2*)(g_pbf + (size_t)lbl * 512);
            acc += row_dist_bf(f, p2, lane);
        }
    }

    // warp reduce
    #pragma unroll
    for (int off = 16; off; off >>= 1)
        acc += __shfl_xor_sync(0xFFFFFFFFu, acc, off);
    if (lane == 0) ssum[wid] = acc;
    __syncthreads();

    // block reduce + publish partial; last block to arrive finishes.
    if (wid == 0) {
        float v = (lane < (BLOCK_THREADS / 32)) ? ssum[lane] : 0.0f;
        #pragma unroll
        for (int off = 4; off; off >>= 1)
            v += __shfl_xor_sync(0xFFFFFFFFu, v, off);
        if (lane == 0) {
            g_partials[blockIdx.x] = v;
            __threadfence();
            unsigned ticket = atomicAdd(&g_done, 1u);
            s_last = (ticket == GRID_BLOCKS - 1) ? 1 : 0;
        }
    }
    __syncthreads();

    if (s_last) {
        __threadfence();  // all g_partials writes visible
        __shared__ double dsum[BLOCK_THREADS / 32];
        double d = 0.0;
        for (int i = threadIdx.x; i < GRID_BLOCKS; i += BLOCK_THREADS)
            d += (double)g_partials[i];
        #pragma unroll
        for (int off = 16; off; off >>= 1)
            d += __shfl_xor_sync(0xFFFFFFFFu, d, off);
        if (lane == 0) dsum[wid] = d;
        __syncthreads();
        if (wid == 0) {
            double t = (lane < (BLOCK_THREADS / 32)) ? dsum[lane] : 0.0;
            #pragma unroll
            for (int off = 4; off; off >>= 1)
                t += __shfl_xor_sync(0xFFFFFFFFu, t, off);
            if (lane == 0) {
                out[0] = (float)(t * (1.0 / (double)N_ROWS));
                g_done = 0u;   // reset for next graph replay
            }
        }
    }
}

extern "C" void kernel_launch(void* const* d_in, const int* in_sizes, int n_in,
                              void* d_out, int out_size) {
    const float4* feat   = 0;
    const void*   labels = 0;
    const float4* protos = 0;
    for (int i = 0; i < n_in; i++) {
        if (in_sizes[i] == N_ROWS * 512)          feat   = (const float4*)d_in[i];
        else if (in_sizes[i] == N_CLASSES * 512)  protos = (const float4*)d_in[i];
        else                                      labels = d_in[i];
    }
    float* out = (float*)d_out;

    convert_kernel<<<(N_CLASSES * D_VEC + 255) / 256, 256>>>(protos);
    proto_loss_kernel<<<GRID_BLOCKS, BLOCK_THREADS>>>(feat, labels, out);
}